// round 16
// baseline (speedup 1.0000x reference)
#include <cuda_runtime.h>
#include <cuda_fp16.h>
#include <cstdint>

// ---------------- problem constants ----------------
#define SQ   4096
#define BB   8
#define HID  1024
#define KTOT 1024
#define MTOT (SQ*BB)          // 32768
#define NTOT (3*HID)          // 3072
#define BH   (BB*HID)         // 8192
#define GSZ  ((size_t)MTOT*HID)

// ---------------- GEMM tiling ----------------
#define BM   128
#define BN   128
#define BK   64               // K halves per chunk (4 k16 phases)
#define NCHK (KTOT/BK)        // 16
#define NSTG 3
#define STRD 72               // padded row stride in halves (144B): conflict-free ldmatrix
#define ST2  (STRD*2)         // 144
#define A_BYTES (BM*ST2)      // 18432
#define B_BYTES (BN*ST2)      // 18432
#define STG_BYTES (A_BYTES + B_BYTES)   // 36864
#define SMEM_TOTAL (NSTG*STG_BYTES)     // 110592 -> 2 CTA/SM (221KB < 228KB)

// ---------------- scan chunking ----------------
#define TCH 256
#define NCH (SQ/TCH)          // 16
#define BH2 (BH/2)            // 4096 channel pairs

// ---------------- scratch ----------------
__device__ __half   g_gates[3*GSZ];            // Z, F, G planes (activated, fp16)
__device__ __half   g_xh[(size_t)MTOT*KTOT];   // X as fp16
__device__ __half   g_wh[(size_t)NTOT*KTOT];   // W as fp16
__device__ float    g_chA[NCH*BH];
__device__ float    g_chB[NCH*BH];
__device__ float    g_cin[NCH*BH];

// ---------------- PTX helpers ----------------
__device__ __forceinline__ uint32_t smem_u32(const void* p) {
    uint32_t a;
    asm("{ .reg .u64 t; cvta.to.shared.u64 t, %1; cvt.u32.u64 %0, t; }" : "=r"(a) : "l"(p));
    return a;
}
#define CP16(dst, src) \
    asm volatile("cp.async.cg.shared.global [%0], [%1], 16;" :: "r"(dst), "l"(src))

__device__ __forceinline__ void ldsm4(uint32_t* r, uint32_t addr) {
    asm volatile("ldmatrix.sync.aligned.m8n8.x4.shared.b16 {%0,%1,%2,%3}, [%4];"
                 : "=r"(r[0]), "=r"(r[1]), "=r"(r[2]), "=r"(r[3]) : "r"(addr));
}
__device__ __forceinline__ void mma_f16(float* d, const uint32_t* a, const uint32_t* b) {
    asm volatile(
        "mma.sync.aligned.m16n8k16.row.col.f32.f16.f16.f32 "
        "{%0,%1,%2,%3}, {%4,%5,%6,%7}, {%8,%9}, {%0,%1,%2,%3};"
        : "+f"(d[0]), "+f"(d[1]), "+f"(d[2]), "+f"(d[3])
        : "r"(a[0]), "r"(a[1]), "r"(a[2]), "r"(a[3]), "r"(b[0]), "r"(b[1]));
}

// ============================================================================
// No-op kernel: keeps gemm_mma at launch index 3 for the ncu capture window.
// ============================================================================
__global__ void noop_k() {}

// ============================================================================
// Pre-convert fp32 -> fp16 for X and W in one launch (4 floats -> uint2).
// ============================================================================
#define XN4 ((int)((size_t)MTOT*KTOT/4))
#define WN4 ((int)((size_t)NTOT*KTOT/4))
__global__ __launch_bounds__(256) void conv_f16(const float* __restrict__ X,
                                                const float* __restrict__ W) {
    int i = blockIdx.x * 256 + threadIdx.x;
    const float4* src;
    uint2* dst;
    int idx;
    if (i < XN4) { src = (const float4*)X; dst = (uint2*)g_xh; idx = i; }
    else if (i < XN4 + WN4) { src = (const float4*)W; dst = (uint2*)g_wh; idx = i - XN4; }
    else return;
    float4 v = src[idx];
    __half2 lo = __floats2half2_rn(v.x, v.y);
    __half2 hi = __floats2half2_rn(v.z, v.w);
    uint2 o;
    o.x = *(uint32_t*)&lo;
    o.y = *(uint32_t*)&hi;
    dst[idx] = o;
}

// ============================================================================
// fp16 m16n8k16 GEMM + fused activations -> fp16 gate planes.
// CTA 128x128, 256 threads (8 warps: 4m x 2n), warp tile 32x64.
// BK=64 chunks (4 k16 phases), 3-stage cp.async ring: the group awaited at
// each barrier was issued TWO chunks earlier -> cp.async latency fully hidden.
// Dual fragment buffers: LDSM of phase p+1 overlaps the HMMA drain of phase p,
// including across the chunk barrier.
// ============================================================================
__global__ __launch_bounds__(256, 2) void gemm_mma(const float* __restrict__ bias) {
    extern __shared__ __half smem[];
    const uint32_t sb = smem_u32(smem);
    const int tid = threadIdx.x;
    const int wid = tid >> 5;
    const int lid = tid & 31;
    const int m0 = blockIdx.y * BM;
    const int n0 = blockIdx.x * BN;

    const int warp_m = (wid & 3) * 32;     // 0,32,64,96
    const int warp_n = (wid >> 2) * 64;    // 0,64

    const __half* Xb = g_xh + (size_t)m0 * KTOT;
    const __half* Wb = g_wh + (size_t)n0 * KTOT;

    float acc[2][8][4];
#pragma unroll
    for (int mf = 0; mf < 2; mf++)
#pragma unroll
        for (int nf = 0; nf < 8; nf++)
#pragma unroll
            for (int q = 0; q < 4; q++) acc[mf][nf][q] = 0.f;

    // chunk: A 128 rows x 128B (8 x 16B) + B same = 2048 CP16 / 256 thr = 8
    auto load_chunk = [&](int c, int s) {
        const uint32_t abase = sb + s * STG_BYTES;
        const uint32_t bbase = abase + A_BYTES;
        const int kc = c * BK;
#pragma unroll
        for (int p = 0; p < 4; p++) {
            int seg = tid + p * 256;           // 0..1023
            int row = seg >> 3, ks = seg & 7;
            CP16(abase + row * ST2 + ks * 16,
                 Xb + (size_t)row * KTOT + kc + ks * 8);
        }
#pragma unroll
        for (int p = 0; p < 4; p++) {
            int seg = tid + p * 256;
            int row = seg >> 3, ks = seg & 7;
            CP16(bbase + row * ST2 + ks * 16,
                 Wb + (size_t)row * KTOT + kc + ks * 8);
        }
        asm volatile("cp.async.commit_group;" ::: "memory");
    };

    // ldmatrix per-thread addressing (proven mapping)
    const int a_row  = lid & 15;
    const int a_byte = (lid >> 4) * 16;
    const int b_row  = (lid & 7) + 8 * (lid >> 4);
    const int b_byte = ((lid >> 3) & 1) * 16;
    const uint32_t a_off = (warp_m + a_row) * ST2 + a_byte;
    const uint32_t b_off = A_BYTES + (warp_n + b_row) * ST2 + b_byte;

    uint32_t afA[2][4], bfA[8][2];   // fragment buffer A (even phases)
    uint32_t afB[2][4], bfB[8][2];   // fragment buffer B (odd phases)

    auto ldfragA = [&](int slot, int kk) {
        const uint32_t base = sb + slot * STG_BYTES;
        ldsm4(afA[0], base + a_off + kk);
        ldsm4(afA[1], base + a_off + 16 * ST2 + kk);
#pragma unroll
        for (int np = 0; np < 4; np++)
            ldsm4(&bfA[2 * np][0], base + b_off + np * 16 * ST2 + kk);
    };
    auto ldfragB = [&](int slot, int kk) {
        const uint32_t base = sb + slot * STG_BYTES;
        ldsm4(afB[0], base + a_off + kk);
        ldsm4(afB[1], base + a_off + 16 * ST2 + kk);
#pragma unroll
        for (int np = 0; np < 4; np++)
            ldsm4(&bfB[2 * np][0], base + b_off + np * 16 * ST2 + kk);
    };

#define HMMA_PACK(af, bf) \
    _Pragma("unroll") \
    for (int mf = 0; mf < 2; mf++) \
        _Pragma("unroll") \
        for (int nf = 0; nf < 8; nf++) \
            mma_f16(acc[mf][nf], (af)[mf], (bf)[nf]);

    // prologue: 3 chunks in flight; chunk 0 resident; preload (0, phase0)
    load_chunk(0, 0);
    load_chunk(1, 1);
    load_chunk(2, 2);
    asm volatile("cp.async.wait_group 2;" ::: "memory");
    __syncthreads();
    ldfragA(0, 0);

    int su = 0;                                // slot of chunk c
    for (int c = 0; c < NCHK; c++) {
        ldfragB(su, 32);                       // phase 1
        HMMA_PACK(afA, bfA)                    // phase 0
        ldfragA(su, 64);                       // phase 2
        HMMA_PACK(afB, bfB)                    // phase 1
        ldfragB(su, 96);                       // phase 3
        HMMA_PACK(afA, bfA)                    // phase 2

        const int sn = (su == NSTG - 1) ? 0 : su + 1;   // slot of chunk c+1
        if (c < NCHK - 1) {
            // pending groups {c+1, c+2}: wait_group 1 publishes c+1, whose
            // cp.async was issued two chunks (~7K cyc) ago -> no latency hit.
            asm volatile("cp.async.wait_group 1;" ::: "memory");
            __syncthreads();
            ldfragA(sn, 0);                    // (c+1, phase 0)
            // slot su's readers all finished (sync above) -> safe to recycle
            if (c + 3 < NCHK) load_chunk(c + 3, su);
        }

        HMMA_PACK(afB, bfB)                    // phase 3
        su = sn;
    }

    // ---- epilogue: bias + activation, write fp16 gate plane ----
    const int lr = lid >> 2;
    const int lc = lid & 3;
    const int gate  = blockIdx.x >> 3;          // 8 x-blocks of 128 per gate
    const int hcol0 = (blockIdx.x & 7) * BN;
    __half* gout = g_gates + (size_t)gate * GSZ;

#pragma unroll
    for (int mf = 0; mf < 2; mf++) {
#pragma unroll
        for (int nf = 0; nf < 8; nf++) {
            const int ncol = warp_n + nf * 8 + 2 * lc;
            const float b0 = __ldg(&bias[n0 + ncol]);
            const float b1 = __ldg(&bias[n0 + ncol + 1]);
#pragma unroll
            for (int half_ = 0; half_ < 2; half_++) {
                const int m = m0 + warp_m + mf * 16 + lr + half_ * 8;
                float y0 = acc[mf][nf][2 * half_ + 0] + b0;
                float y1 = acc[mf][nf][2 * half_ + 1] + b1;
                float v0, v1;
                if (gate == 0) {
                    v0 = 2.f / (1.f + __expf(-2.f * y0)) - 1.f;  // tanh
                    v1 = 2.f / (1.f + __expf(-2.f * y1)) - 1.f;
                } else {
                    v0 = 1.f / (1.f + __expf(-y0));              // sigmoid
                    v1 = 1.f / (1.f + __expf(-y1));
                }
                *(__half2*)(gout + (size_t)m * HID + hcol0 + ncol) =
                    __floats2half2_rn(v0, v1);
            }
        }
    }
}

// ============================================================================
// Scan phase A: per-chunk affine composition (fp16 gates, 2 channels/thread).
// ============================================================================
__global__ __launch_bounds__(256) void scanA() {
    const int j2 = blockIdx.x * 256 + threadIdx.x;
    const int ch = blockIdx.y;
    const __half2* Zp = (const __half2*)g_gates;
    const __half2* Fp = (const __half2*)(g_gates + GSZ);

    float2 A = make_float2(1.f, 1.f);
    float2 Bv = make_float2(0.f, 0.f);
    size_t base = (size_t)ch * TCH * BH2 + j2;
#pragma unroll 8
    for (int s = 0; s < TCH; s++) {
        size_t idx = base + (size_t)s * BH2;
        float2 f = __half22float2(Fp[idx]);
        float2 z = __half22float2(Zp[idx]);
        float ox = 1.f - f.x, oy = 1.f - f.y;
        A.x *= ox;                    A.y *= oy;
        Bv.x = f.x * z.x + ox * Bv.x; Bv.y = f.y * z.y + oy * Bv.y;
    }
    ((float2*)g_chA)[ch * BH2 + j2] = A;
    ((float2*)g_chB)[ch * BH2 + j2] = Bv;
}

// ============================================================================
// Scan phase B: sequential over 16 chunk states; records per-chunk carry.
// ============================================================================
__global__ __launch_bounds__(256) void scanB(const float* __restrict__ hidden,
                                             float* __restrict__ c_last) {
    const int j = blockIdx.x * 256 + threadIdx.x;
    float c = hidden[j];
#pragma unroll 8
    for (int i = 0; i < NCH; i++) {
        g_cin[i * BH + j] = c;
        c = g_chB[i * BH + j] + g_chA[i * BH + j] * c;
    }
    c_last[j] = c;
}

// ============================================================================
// Scan phase C: re-scan chunks with correct carries; write C and H (fp32).
// ============================================================================
__global__ __launch_bounds__(256) void scanC(float* __restrict__ Hout,
                                             float* __restrict__ Cout) {
    const int j2 = blockIdx.x * 256 + threadIdx.x;
    const int ch = blockIdx.y;
    const __half2* Zp = (const __half2*)g_gates;
    const __half2* Fp = (const __half2*)(g_gates + GSZ);
    const __half2* Gp = (const __half2*)(g_gates + 2 * GSZ);

    float2 c = ((const float2*)g_cin)[ch * BH2 + j2];
    size_t base = (size_t)ch * TCH * BH2 + j2;
#pragma unroll 4
    for (int s = 0; s < TCH; s++) {
        size_t idx = base + (size_t)s * BH2;
        float2 f = __half22float2(Fp[idx]);
        float2 z = __half22float2(Zp[idx]);
        float2 g = __half22float2(Gp[idx]);
        c.x = f.x * z.x + (1.f - f.x) * c.x;
        c.y = f.y * z.y + (1.f - f.y) * c.y;
        ((float2*)Cout)[idx] = c;
        ((float2*)Hout)[idx] = make_float2(g.x * c.x, g.y * c.y);
    }
}

// ============================================================================
// Launch: conv, noop, noop, gemm (ncu captures launch idx 3), scans.
// ============================================================================
extern "C" void kernel_launch(void* const* d_in, const int* in_sizes, int n_in,
                              void* d_out, int out_size) {
    const float* X      = (const float*)d_in[0];
    const float* hidden = (const float*)d_in[1];
    const float* W      = (const float*)d_in[2];
    const float* bias   = (const float*)d_in[3];

    float* out   = (float*)d_out;
    float* Hout  = out;
    float* Clast = out + GSZ;
    float* Cout  = out + GSZ + BH;

    cudaFuncSetAttribute(gemm_mma, cudaFuncAttributeMaxDynamicSharedMemorySize, SMEM_TOTAL);

    const int ctot = XN4 + WN4;
    conv_f16<<<(ctot + 255) / 256, 256>>>(X, W);
    noop_k<<<1, 32>>>();
    noop_k<<<1, 32>>>();
    gemm_mma<<<dim3(NTOT / BN, MTOT / BM), 256, SMEM_TOTAL>>>(bias);
    scanA<<<dim3(BH2 / 256, NCH), 256>>>();
    scanB<<<BH / 256, 256>>>(hidden, Clast);
    scanC<<<dim3(BH2 / 256, NCH), 256>>>(Hout, Cout);
}

// round 17
// speedup vs baseline: 1.0416x; 1.0416x over previous
#include <cuda_runtime.h>
#include <cuda_fp16.h>
#include <cstdint>

// ---------------- problem constants ----------------
#define SQ   4096
#define BB   8
#define HID  1024
#define KTOT 1024
#define MTOT (SQ*BB)          // 32768
#define NTOT (3*HID)          // 3072
#define BH   (BB*HID)         // 8192
#define GSZ  ((size_t)MTOT*HID)

// ---------------- GEMM tiling ----------------
#define BM   128
#define BN   128
#define BK   64               // K halves per chunk (4 k16 phases)
#define NCHK (KTOT/BK)        // 16
#define NSTG 2
#define STRD 72               // padded row stride in halves (144B): conflict-free ldmatrix
#define ST2  (STRD*2)         // 144
#define A_BYTES (BM*ST2)      // 18432
#define B_BYTES (BN*ST2)      // 18432
#define STG_BYTES (A_BYTES + B_BYTES)   // 36864
#define SMEM_TOTAL (NSTG*STG_BYTES)     // 73728 -> 2 CTA/SM

// ---------------- scan chunking ----------------
#define TCH 128
#define NCH (SQ/TCH)          // 32
#define BH2 (BH/2)            // 4096 channel pairs

// ---------------- scratch ----------------
__device__ __half   g_gates[3*GSZ];            // Z, F, G planes (activated, fp16)
__device__ __half   g_xh[(size_t)MTOT*KTOT];   // X as fp16
__device__ __half   g_wh[(size_t)NTOT*KTOT];   // W as fp16
__device__ float    g_chA[NCH*BH];
__device__ float    g_chB[NCH*BH];
__device__ float    g_cin[NCH*BH];

// ---------------- PTX helpers ----------------
__device__ __forceinline__ uint32_t smem_u32(const void* p) {
    uint32_t a;
    asm("{ .reg .u64 t; cvta.to.shared.u64 t, %1; cvt.u32.u64 %0, t; }" : "=r"(a) : "l"(p));
    return a;
}
#define CP16(dst, src) \
    asm volatile("cp.async.cg.shared.global [%0], [%1], 16;" :: "r"(dst), "l"(src))

__device__ __forceinline__ void ldsm4(uint32_t* r, uint32_t addr) {
    asm volatile("ldmatrix.sync.aligned.m8n8.x4.shared.b16 {%0,%1,%2,%3}, [%4];"
                 : "=r"(r[0]), "=r"(r[1]), "=r"(r[2]), "=r"(r[3]) : "r"(addr));
}
__device__ __forceinline__ void mma_f16(float* d, const uint32_t* a, const uint32_t* b) {
    asm volatile(
        "mma.sync.aligned.m16n8k16.row.col.f32.f16.f16.f32 "
        "{%0,%1,%2,%3}, {%4,%5,%6,%7}, {%8,%9}, {%0,%1,%2,%3};"
        : "+f"(d[0]), "+f"(d[1]), "+f"(d[2]), "+f"(d[3])
        : "r"(a[0]), "r"(a[1]), "r"(a[2]), "r"(a[3]), "r"(b[0]), "r"(b[1]));
}

// ============================================================================
// No-op kernel: keeps gemm_mma at launch index 3 for the ncu capture window.
// ============================================================================
__global__ void noop_k() {}

// ============================================================================
// Pre-convert fp32 -> fp16 for X and W in one launch (4 floats -> uint2).
// ============================================================================
#define XN4 ((int)((size_t)MTOT*KTOT/4))
#define WN4 ((int)((size_t)NTOT*KTOT/4))
__global__ __launch_bounds__(256) void conv_f16(const float* __restrict__ X,
                                                const float* __restrict__ W) {
    int i = blockIdx.x * 256 + threadIdx.x;
    const float4* src;
    uint2* dst;
    int idx;
    if (i < XN4) { src = (const float4*)X; dst = (uint2*)g_xh; idx = i; }
    else if (i < XN4 + WN4) { src = (const float4*)W; dst = (uint2*)g_wh; idx = i - XN4; }
    else return;
    float4 v = src[idx];
    __half2 lo = __floats2half2_rn(v.x, v.y);
    __half2 hi = __floats2half2_rn(v.z, v.w);
    uint2 o;
    o.x = *(uint32_t*)&lo;
    o.y = *(uint32_t*)&hi;
    dst[idx] = o;
}

// ============================================================================
// fp16 m16n8k16 GEMM + fused activations -> fp16 gate planes.
// CTA 128x128, 256 threads (8 warps: 4m x 2n), warp tile 32x64.
// BK=64 chunks (4 k16 phases), 2-stage ring -> ONE barrier per 4 phases.
// Dual fragment buffers: LDSM of phase p+1 overlaps HMMA drain of phase p,
// including across the chunk barrier. Compile-time stage slots (unroll x2).
// ============================================================================
__global__ __launch_bounds__(256, 2) void gemm_mma(const float* __restrict__ bias) {
    extern __shared__ __half smem[];
    const uint32_t sb = smem_u32(smem);
    const int tid = threadIdx.x;
    const int wid = tid >> 5;
    const int lid = tid & 31;
    const int m0 = blockIdx.y * BM;
    const int n0 = blockIdx.x * BN;

    const int warp_m = (wid & 3) * 32;     // 0,32,64,96
    const int warp_n = (wid >> 2) * 64;    // 0,64

    const __half* Xb = g_xh + (size_t)m0 * KTOT;
    const __half* Wb = g_wh + (size_t)n0 * KTOT;

    float acc[2][8][4];
#pragma unroll
    for (int mf = 0; mf < 2; mf++)
#pragma unroll
        for (int nf = 0; nf < 8; nf++)
#pragma unroll
            for (int q = 0; q < 4; q++) acc[mf][nf][q] = 0.f;

    // chunk: A 128 rows x 128B (8 x 16B) + B same = 2048 CP16 / 256 thr = 8
    auto load_chunk = [&](int c, int s) {
        const uint32_t abase = sb + s * STG_BYTES;
        const uint32_t bbase = abase + A_BYTES;
        const int kc = c * BK;
#pragma unroll
        for (int p = 0; p < 4; p++) {
            int seg = tid + p * 256;           // 0..1023
            int row = seg >> 3, ks = seg & 7;
            CP16(abase + row * ST2 + ks * 16,
                 Xb + (size_t)row * KTOT + kc + ks * 8);
        }
#pragma unroll
        for (int p = 0; p < 4; p++) {
            int seg = tid + p * 256;
            int row = seg >> 3, ks = seg & 7;
            CP16(bbase + row * ST2 + ks * 16,
                 Wb + (size_t)row * KTOT + kc + ks * 8);
        }
        asm volatile("cp.async.commit_group;" ::: "memory");
    };

    // ldmatrix per-thread addressing (proven mapping)
    const int a_row  = lid & 15;
    const int a_byte = (lid >> 4) * 16;
    const int b_row  = (lid & 7) + 8 * (lid >> 4);
    const int b_byte = ((lid >> 3) & 1) * 16;
    const uint32_t a_off = (warp_m + a_row) * ST2 + a_byte;
    const uint32_t b_off = A_BYTES + (warp_n + b_row) * ST2 + b_byte;

    uint32_t afA[2][4], bfA[8][2];   // fragment buffer A (even phases)
    uint32_t afB[2][4], bfB[8][2];   // fragment buffer B (odd phases)

    auto ldfragA = [&](int slot, int kk) {
        const uint32_t base = sb + slot * STG_BYTES;
        ldsm4(afA[0], base + a_off + kk);
        ldsm4(afA[1], base + a_off + 16 * ST2 + kk);
#pragma unroll
        for (int np = 0; np < 4; np++)
            ldsm4(&bfA[2 * np][0], base + b_off + np * 16 * ST2 + kk);
    };
    auto ldfragB = [&](int slot, int kk) {
        const uint32_t base = sb + slot * STG_BYTES;
        ldsm4(afB[0], base + a_off + kk);
        ldsm4(afB[1], base + a_off + 16 * ST2 + kk);
#pragma unroll
        for (int np = 0; np < 4; np++)
            ldsm4(&bfB[2 * np][0], base + b_off + np * 16 * ST2 + kk);
    };

#define HMMA_PACK(af, bf) \
    _Pragma("unroll") \
    for (int mf = 0; mf < 2; mf++) \
        _Pragma("unroll") \
        for (int nf = 0; nf < 8; nf++) \
            mma_f16(acc[mf][nf], (af)[mf], (bf)[nf]);

    // prologue: 2 chunks in flight; chunk 0 resident; preload (0, phase0)
    load_chunk(0, 0);
    load_chunk(1, 1);
    asm volatile("cp.async.wait_group 1;" ::: "memory");
    __syncthreads();
    ldfragA(0, 0);

    for (int cb = 0; cb < NCHK; cb += 2) {
#pragma unroll
        for (int u = 0; u < 2; u++) {          // slot == u (compile-time)
            const int c = cb + u;

            ldfragB(u, 32);                    // phase 1
            HMMA_PACK(afA, bfA)                // phase 0
            ldfragA(u, 64);                    // phase 2
            HMMA_PACK(afB, bfB)                // phase 1
            ldfragB(u, 96);                    // phase 3
            HMMA_PACK(afA, bfA)                // phase 2

            if (c < NCHK - 1) {
                // publish chunk c+1 (only pending group), recycle slot u
                asm volatile("cp.async.wait_group 0;" ::: "memory");
                __syncthreads();
                ldfragA(u ^ 1, 0);             // (c+1, phase 0)
                if (c + 2 < NCHK) load_chunk(c + 2, u);
            }

            HMMA_PACK(afB, bfB)                // phase 3
        }
    }

    // ---- epilogue: bias + activation, write fp16 gate plane ----
    const int lr = lid >> 2;
    const int lc = lid & 3;
    const int gate  = blockIdx.x >> 3;          // 8 x-blocks of 128 per gate
    const int hcol0 = (blockIdx.x & 7) * BN;
    __half* gout = g_gates + (size_t)gate * GSZ;

#pragma unroll
    for (int mf = 0; mf < 2; mf++) {
#pragma unroll
        for (int nf = 0; nf < 8; nf++) {
            const int ncol = warp_n + nf * 8 + 2 * lc;
            const float b0 = __ldg(&bias[n0 + ncol]);
            const float b1 = __ldg(&bias[n0 + ncol + 1]);
#pragma unroll
            for (int half_ = 0; half_ < 2; half_++) {
                const int m = m0 + warp_m + mf * 16 + lr + half_ * 8;
                float y0 = acc[mf][nf][2 * half_ + 0] + b0;
                float y1 = acc[mf][nf][2 * half_ + 1] + b1;
                float v0, v1;
                if (gate == 0) {
                    v0 = 2.f / (1.f + __expf(-2.f * y0)) - 1.f;  // tanh
                    v1 = 2.f / (1.f + __expf(-2.f * y1)) - 1.f;
                } else {
                    v0 = 1.f / (1.f + __expf(-y0));              // sigmoid
                    v1 = 1.f / (1.f + __expf(-y1));
                }
                *(__half2*)(gout + (size_t)m * HID + hcol0 + ncol) =
                    __floats2half2_rn(v0, v1);
            }
        }
    }
}

// ============================================================================
// Scan phase A: per-chunk affine composition (fp16 gates, 2 channels/thread).
// ============================================================================
__global__ __launch_bounds__(256) void scanA() {
    const int j2 = blockIdx.x * 256 + threadIdx.x;
    const int ch = blockIdx.y;
    const __half2* Zp = (const __half2*)g_gates;
    const __half2* Fp = (const __half2*)(g_gates + GSZ);

    float2 A = make_float2(1.f, 1.f);
    float2 Bv = make_float2(0.f, 0.f);
    size_t base = (size_t)ch * TCH * BH2 + j2;
#pragma unroll 8
    for (int s = 0; s < TCH; s++) {
        size_t idx = base + (size_t)s * BH2;
        float2 f = __half22float2(Fp[idx]);
        float2 z = __half22float2(Zp[idx]);
        float ox = 1.f - f.x, oy = 1.f - f.y;
        A.x *= ox;                    A.y *= oy;
        Bv.x = f.x * z.x + ox * Bv.x; Bv.y = f.y * z.y + oy * Bv.y;
    }
    ((float2*)g_chA)[ch * BH2 + j2] = A;
    ((float2*)g_chB)[ch * BH2 + j2] = Bv;
}

// ============================================================================
// Scan phase B: prefetch all 32 chunk states (independent loads, MLP=64),
// then a register-resident sequential chain, then independent stores.
// ============================================================================
__global__ __launch_bounds__(256) void scanB(const float* __restrict__ hidden,
                                             float* __restrict__ c_last) {
    const int j = blockIdx.x * 256 + threadIdx.x;

    float a[NCH], b[NCH];
#pragma unroll
    for (int i = 0; i < NCH; i++) {
        a[i] = g_chA[i * BH + j];
        b[i] = g_chB[i * BH + j];
    }
    float cin[NCH];
    float c = hidden[j];
#pragma unroll
    for (int i = 0; i < NCH; i++) {
        cin[i] = c;
        c = b[i] + a[i] * c;
    }
#pragma unroll
    for (int i = 0; i < NCH; i++)
        g_cin[i * BH + j] = cin[i];
    c_last[j] = c;
}

// ============================================================================
// Scan phase C: re-scan chunks with correct carries; write C and H (fp32).
// ============================================================================
__global__ __launch_bounds__(256) void scanC(float* __restrict__ Hout,
                                             float* __restrict__ Cout) {
    const int j2 = blockIdx.x * 256 + threadIdx.x;
    const int ch = blockIdx.y;
    const __half2* Zp = (const __half2*)g_gates;
    const __half2* Fp = (const __half2*)(g_gates + GSZ);
    const __half2* Gp = (const __half2*)(g_gates + 2 * GSZ);

    float2 c = ((const float2*)g_cin)[ch * BH2 + j2];
    size_t base = (size_t)ch * TCH * BH2 + j2;
#pragma unroll 4
    for (int s = 0; s < TCH; s++) {
        size_t idx = base + (size_t)s * BH2;
        float2 f = __half22float2(Fp[idx]);
        float2 z = __half22float2(Zp[idx]);
        float2 g = __half22float2(Gp[idx]);
        c.x = f.x * z.x + (1.f - f.x) * c.x;
        c.y = f.y * z.y + (1.f - f.y) * c.y;
        ((float2*)Cout)[idx] = c;
        ((float2*)Hout)[idx] = make_float2(g.x * c.x, g.y * c.y);
    }
}

// ============================================================================
// Launch: conv, noop, noop, gemm (ncu captures launch idx 3), scans.
// ============================================================================
extern "C" void kernel_launch(void* const* d_in, const int* in_sizes, int n_in,
                              void* d_out, int out_size) {
    const float* X      = (const float*)d_in[0];
    const float* hidden = (const float*)d_in[1];
    const float* W      = (const float*)d_in[2];
    const float* bias   = (const float*)d_in[3];

    float* out   = (float*)d_out;
    float* Hout  = out;
    float* Clast = out + GSZ;
    float* Cout  = out + GSZ + BH;

    cudaFuncSetAttribute(gemm_mma, cudaFuncAttributeMaxDynamicSharedMemorySize, SMEM_TOTAL);

    const int ctot = XN4 + WN4;
    conv_f16<<<(ctot + 255) / 256, 256>>>(X, W);
    noop_k<<<1, 32>>>();
    noop_k<<<1, 32>>>();
    gemm_mma<<<dim3(NTOT / BN, MTOT / BM), 256, SMEM_TOTAL>>>(bias);
    scanA<<<dim3(BH2 / 256, NCH), 256>>>();
    scanB<<<BH / 256, 256>>>(hidden, Clast);
    scanC<<<dim3(BH2 / 256, NCH), 256>>>(Hout, Cout);
}